// round 14
// baseline (speedup 1.0000x reference)
#include <cuda_runtime.h>

typedef unsigned long long u64;
typedef unsigned int u32;

// ---- packed f32x2 helpers (Blackwell FFMA2 path) ----
__device__ __forceinline__ void fma2(u64 &d, u64 a, u64 b) {
    asm volatile("fma.rn.f32x2 %0, %1, %2, %0;" : "+l"(d) : "l"(a), "l"(b));
}
__device__ __forceinline__ u64 dup2(float x) {
    u64 r; asm("mov.b64 %0, {%1, %1};" : "=l"(r) : "f"(x)); return r;
}
__device__ __forceinline__ float2 unpk(u64 v) {
    float lo, hi; asm("mov.b64 {%0, %1}, %2;" : "=f"(lo), "=f"(hi) : "l"(v));
    return make_float2(lo, hi);
}
__device__ __forceinline__ void cp16(u32 dst, const float* src) {
    asm volatile("cp.async.cg.shared.global [%0], [%1], 16;" :: "r"(dst), "l"(src));
}
__device__ __forceinline__ void cp_commit() { asm volatile("cp.async.commit_group;"); }
__device__ __forceinline__ void cp_wait0()  { asm volatile("cp.async.wait_group 0;"); }

#define VSEL(v,u) ((u)==0?(v).x:(u)==1?(v).y:(u)==2?(v).z:(v).w)

// q:(4,16,1024,64) k:(4,16,64,1024) v:(4,16,1024,64)
// prev:(4,16,1024,1024) mask:(1,16,1024,1024) scale:(1)
// out tuple: output ++ weights ++ scores

#define WS 132       // w_s row stride
#define WBUF 4224    // one w_s buffer (32 * 132)

// smem floats:
//  [0,2048)        q_s (pass A q^T)
//  [2048,18432)    kv_s: K [64][256] (pass A) | pass B stage bufs 2 x (scores 4096 + mask 4096)
//                  | combine scratch (3*2176) at the end
//  [18432,26880)   w_s double buffer: 2 x [32][132]
//  [26880,26944)   rsum_p[64]    [26944,26976) rinv[32]
#define SMEM_FLOATS 26976
#define SMEM_BYTES  (SMEM_FLOATS * 4)

__global__ void __launch_bounds__(256, 2)
attn_fused6_kernel(const float* __restrict__ q, const float* __restrict__ k,
                   const float* __restrict__ v, const float* __restrict__ prev,
                   const float* __restrict__ mask, const float* __restrict__ scale_p,
                   float* __restrict__ out, float* __restrict__ wts, float* __restrict__ scr)
{
    extern __shared__ float sm[];
    float* q_s     = sm;                // 2048
    float* kv_s    = sm + 2048;         // 16384 (K chunk / stage bufs / scratch)
    float* w_s     = sm + 18432;        // 2 x 4224
    float* scratch = kv_s;              // combine scratch (stage bufs dead by then)
    float* rsum_p  = sm + 26880;        // [64]
    float* rinv    = sm + 26944;        // [32]

    const int tid = threadIdx.x;
    const int bid = blockIdx.x;
    const int qt  = bid & 31;
    const int bh  = bid >> 5;
    const int h   = bh & 15;

    const float scale = scale_p[0];

    const float* qp = q    + ((size_t)bh * 1024 + (size_t)qt * 32) * 64;
    const float* kp = k    + (size_t)bh * 65536;
    const float* vp = v    + (size_t)bh * 65536;
    const float* pp = prev + ((size_t)bh * 1024 + (size_t)qt * 32) * 1024;
    const float* mp = mask + ((size_t)h  * 1024 + (size_t)qt * 32) * 1024;
    float* op = out + ((size_t)bh * 1024 + (size_t)qt * 32) * 64;
    float* wp = wts + ((size_t)bh * 1024 + (size_t)qt * 32) * 1024;
    float* sp = scr + ((size_t)bh * 1024 + (size_t)qt * 32) * 1024;

    const u32 kv_sh = (u32)__cvta_generic_to_shared(kv_s);

    // ---- stage K chunk 0 ----
    #pragma unroll
    for (int j = 0; j < 16; j++) {
        int idx = j * 1024 + tid * 4;
        int d = idx >> 8, s = idx & 255;
        cp16(kv_sh + idx * 4, kp + d * 1024 + s);
    }
    cp_commit();

    // ---- Q tile (32x64) transposed into q_s[d*32 + r] (rows contiguous -> u64 pairs) ----
    #pragma unroll
    for (int i = 0; i < 2; i++) {
        int idx = i * 1024 + tid * 4;
        float4 val = *(const float4*)(qp + idx);
        int r = idx >> 6, d0 = idx & 63;
        q_s[(d0 + 0) * 32 + r] = val.x;
        q_s[(d0 + 1) * 32 + r] = val.y;
        q_s[(d0 + 2) * 32 + r] = val.z;
        q_s[(d0 + 3) * 32 + r] = val.w;
    }

    const int w  = tid >> 5;
    const int tx = tid & 31;

    // =============== Pass A: scores = qk*scale + prev ; exp + rowsum fused ===============
    // 8 warps = 4 rowgroups (8 rows) x 2 sgroups; lane tile = 4 row-PAIRS x 4 consecutive s
    // k is dup'd (4/iter), q rows come as natural f32x2 pairs from q_s.
    const int rg = w >> 1, sgA = w & 1;
    const int r0 = rg * 8;
    const int sA4 = sgA * 128 + tx * 4;     // local s in [0,256), 4 consecutive

    float lsum[8];
    #pragma unroll
    for (int i = 0; i < 8; i++) lsum[i] = 0.f;

    for (int c = 0; c < 4; c++) {
        // prefetch prev for this chunk into registers (lands under the mainloop)
        float4 pf[8];
        #pragma unroll
        for (int i = 0; i < 8; i++)
            pf[i] = *(const float4*)(pp + (r0 + i) * 1024 + c * 256 + sA4);

        cp_wait0();
        __syncthreads();             // K chunk c staged

        u64 acc[4][4];               // [row-pair p][s j]; .x = row r0+2p, .y = row r0+2p+1
        #pragma unroll
        for (int p = 0; p < 4; p++)
            #pragma unroll
            for (int j = 0; j < 4; j++) acc[p][j] = 0ull;

        #pragma unroll 8
        for (int d = 0; d < 64; d++) {
            ulonglong2 qv = *(const ulonglong2*)(q_s + d * 32 + r0);      // pairs p0,p1
            ulonglong2 qw = *(const ulonglong2*)(q_s + d * 32 + r0 + 4);  // pairs p2,p3
            float4 kf = *(const float4*)(kv_s + d * 256 + sA4);
            u64 k0 = dup2(kf.x), k1 = dup2(kf.y), k2 = dup2(kf.z), k3 = dup2(kf.w);
            fma2(acc[0][0], qv.x, k0); fma2(acc[0][1], qv.x, k1);
            fma2(acc[0][2], qv.x, k2); fma2(acc[0][3], qv.x, k3);
            fma2(acc[1][0], qv.y, k0); fma2(acc[1][1], qv.y, k1);
            fma2(acc[1][2], qv.y, k2); fma2(acc[1][3], qv.y, k3);
            fma2(acc[2][0], qw.x, k0); fma2(acc[2][1], qw.x, k1);
            fma2(acc[2][2], qw.x, k2); fma2(acc[2][3], qw.x, k3);
            fma2(acc[3][0], qw.y, k0); fma2(acc[3][1], qw.y, k1);
            fma2(acc[3][2], qw.y, k2); fma2(acc[3][3], qw.y, k3);
        }
        __syncthreads();             // kv_s free of readers

        if (c < 3) {                 // stage next K chunk; flies under the epilogue
            #pragma unroll
            for (int j = 0; j < 16; j++) {
                int idx = j * 1024 + tid * 4;
                int d = idx >> 8, s = idx & 255;
                cp16(kv_sh + idx * 4, kp + d * 1024 + (c + 1) * 256 + s);
            }
            cp_commit();
        }

        // epilogue: regroup pairs -> per-row float4; prev from regs; vectorized stores
        #pragma unroll
        for (int p = 0; p < 4; p++) {
            int re = r0 + 2 * p;
            float2 e0 = unpk(acc[p][0]);
            float2 e1 = unpk(acc[p][1]);
            float2 e2 = unpk(acc[p][2]);
            float2 e3 = unpk(acc[p][3]);
            float4 pv0 = pf[2 * p], pv1 = pf[2 * p + 1];
            float4 sv0, sv1;
            sv0.x = fmaf(e0.x, scale, pv0.x);
            sv0.y = fmaf(e1.x, scale, pv0.y);
            sv0.z = fmaf(e2.x, scale, pv0.z);
            sv0.w = fmaf(e3.x, scale, pv0.w);
            sv1.x = fmaf(e0.y, scale, pv1.x);
            sv1.y = fmaf(e1.y, scale, pv1.y);
            sv1.z = fmaf(e2.y, scale, pv1.z);
            sv1.w = fmaf(e3.y, scale, pv1.w);
            *(float4*)(sp + re * 1024 + c * 256 + sA4)       = sv0;
            *(float4*)(sp + (re + 1) * 1024 + c * 256 + sA4) = sv1;
            lsum[2 * p]     += (__expf(sv0.x) + __expf(sv0.y)) + (__expf(sv0.z) + __expf(sv0.w));
            lsum[2 * p + 1] += (__expf(sv1.x) + __expf(sv1.y)) + (__expf(sv1.z) + __expf(sv1.w));
        }
    }

    // ---- row-sum reduce ----
    #pragma unroll
    for (int i = 0; i < 8; i++) {
        float s = lsum[i];
        #pragma unroll
        for (int off = 16; off; off >>= 1)
            s += __shfl_xor_sync(0xffffffffu, s, off);
        if (tx == 0) rsum_p[sgA * 32 + r0 + i] = s;
    }
    __syncthreads();
    if (tid < 32) rinv[tid] = 1.0f / (rsum_p[tid] + rsum_p[32 + tid]);
    __syncthreads();    // all sp STGs visible before cp.async re-reads

    // =============== Pass B: weights + output GEMM; convert-ahead pipeline ===============
    const u32 st_sh = kv_sh;                     // stage bufs: 2 x (scores 4096 + mask 4096)

    const int sub = w >> 1, dh = w & 1;          // 4 s-subgroups (32 s) x 2 d-halves
    const int txg = tx & 3, tyg = tx >> 2;
    const int dcol = dh * 32 + txg * 8;
    const int rr = tid >> 3, t8 = tid & 7;       // conversion map: 8 threads per row
    const float ivr = rinv[rr];

    // stage(chunk) -> buffer (chunk&1)
    #define STAGE_CHUNK(cc) do {                                                          \
        int _b = (cc) & 1;                                                                \
        _Pragma("unroll")                                                                 \
        for (int j = 0; j < 4; j++) {                                                     \
            int idx = j * 1024 + tid * 4;                                                 \
            int row = idx >> 7, scol = idx & 127;                                         \
            cp16(st_sh + (_b * 8192 + idx) * 4,        sp + row * 1024 + (cc) * 128 + scol); \
            cp16(st_sh + (_b * 8192 + 4096 + idx) * 4, mp + row * 1024 + (cc) * 128 + scol); \
        }                                                                                 \
        cp_commit();                                                                      \
    } while (0)

    // convert(chunk): w = exp(score)*inv*mask -> gmem wts + w_s[chunk&1]
    #define CONVERT_CHUNK(cc) do {                                                        \
        const float* _sb = kv_s + ((cc) & 1) * 8192;                                      \
        const float* _mb = _sb + 4096;                                                    \
        float* _wb = w_s + ((cc) & 1) * WBUF;                                             \
        _Pragma("unroll")                                                                 \
        for (int j = 0; j < 4; j++) {                                                     \
            int sl = t8 * 4 + j * 32;                                                     \
            float4 sv = *(const float4*)(_sb + rr * 128 + sl);                            \
            float4 mv = *(const float4*)(_mb + rr * 128 + sl);                            \
            float4 w4;                                                                    \
            w4.x = __expf(sv.x) * ivr * mv.x;                                             \
            w4.y = __expf(sv.y) * ivr * mv.y;                                             \
            w4.z = __expf(sv.z) * ivr * mv.z;                                             \
            w4.w = __expf(sv.w) * ivr * mv.w;                                             \
            *(float4*)(wp + rr * 1024 + (cc) * 128 + sl) = w4;                            \
            *(float4*)(_wb + rr * WS + sl)               = w4;                            \
        }                                                                                 \
    } while (0)

    u64 oacc[4][4];
    #pragma unroll
    for (int i = 0; i < 4; i++)
        #pragma unroll
        for (int p = 0; p < 4; p++) oacc[i][p] = 0ull;

    // prologue: stage 0, convert 0, stage 1
    STAGE_CHUNK(0);
    cp_wait0();
    __syncthreads();
    CONVERT_CHUNK(0);
    STAGE_CHUNK(1);

    for (int c = 0; c < 8; c++) {
        cp_wait0();                  // own stage(c+1) group done (none at c=7)
        __syncthreads();             // all warps' stage(c+1) + convert(c) visible
        if (c < 7) CONVERT_CHUNK(c + 1);         // writes w_s[(c+1)&1], overlaps GEMM(c)
        if (c < 6) STAGE_CHUNK(c + 2);           // into stage[(c)&1], free since convert(c)

        const float* wbuf = w_s + (c & 1) * WBUF;
        const int sb = sub * 32;
        const float* vbase = vp + ((size_t)(c * 128 + sb)) * 64 + dcol;

        #pragma unroll 2
        for (int ss = 0; ss < 32; ss += 4) {
            float4 wv0 = *(const float4*)(wbuf + (tyg +  0) * WS + sb + ss);
            float4 wv1 = *(const float4*)(wbuf + (tyg +  8) * WS + sb + ss);
            float4 wv2 = *(const float4*)(wbuf + (tyg + 16) * WS + sb + ss);
            float4 wv3 = *(const float4*)(wbuf + (tyg + 24) * WS + sb + ss);
            ulonglong2 va[4], vb[4];
            #pragma unroll
            for (int u = 0; u < 4; u++) {
                va[u] = *(const ulonglong2*)(vbase + (ss + u) * 64);
                vb[u] = *(const ulonglong2*)(vbase + (ss + u) * 64 + 4);
            }
            #pragma unroll
            for (int u = 0; u < 4; u++) {
                u64 w0 = dup2(VSEL(wv0, u));
                u64 w1 = dup2(VSEL(wv1, u));
                u64 w2 = dup2(VSEL(wv2, u));
                u64 w3 = dup2(VSEL(wv3, u));
                fma2(oacc[0][0], w0, va[u].x); fma2(oacc[0][1], w0, va[u].y);
                fma2(oacc[0][2], w0, vb[u].x); fma2(oacc[0][3], w0, vb[u].y);
                fma2(oacc[1][0], w1, va[u].x); fma2(oacc[1][1], w1, va[u].y);
                fma2(oacc[1][2], w1, vb[u].x); fma2(oacc[1][3], w1, vb[u].y);
                fma2(oacc[2][0], w2, va[u].x); fma2(oacc[2][1], w2, va[u].y);
                fma2(oacc[2][2], w2, vb[u].x); fma2(oacc[2][3], w2, vb[u].y);
                fma2(oacc[3][0], w3, va[u].x); fma2(oacc[3][1], w3, va[u].y);
                fma2(oacc[3][2], w3, vb[u].x); fma2(oacc[3][3], w3, vb[u].y);
            }
        }
    }

    // ---- combine the 4 s-subgroup partials (stage bufs dead -> scratch in kv_s) ----
    __syncthreads();
    if (sub > 0) {
        #pragma unroll
        for (int i = 0; i < 4; i++) {
            float2 p0 = unpk(oacc[i][0]), p1 = unpk(oacc[i][1]);
            float2 p2 = unpk(oacc[i][2]), p3 = unpk(oacc[i][3]);
            float* bptr = scratch + (sub - 1) * 2176 + (tyg + 8 * i) * 68 + dcol;
            *(float4*)(bptr)     = make_float4(p0.x, p0.y, p1.x, p1.y);
            *(float4*)(bptr + 4) = make_float4(p2.x, p2.y, p3.x, p3.y);
        }
    }
    __syncthreads();
    if (sub == 0) {
        #pragma unroll
        for (int i = 0; i < 4; i++) {
            int row = tyg + 8 * i;
            float2 p0 = unpk(oacc[i][0]), p1 = unpk(oacc[i][1]);
            float2 p2 = unpk(oacc[i][2]), p3 = unpk(oacc[i][3]);
            float4 lo = make_float4(p0.x, p0.y, p1.x, p1.y);
            float4 hi = make_float4(p2.x, p2.y, p3.x, p3.y);
            #pragma unroll
            for (int s2 = 0; s2 < 3; s2++) {
                const float* bptr = scratch + s2 * 2176 + row * 68 + dcol;
                float4 a  = *(const float4*)(bptr);
                float4 b2 = *(const float4*)(bptr + 4);
                lo.x += a.x;  lo.y += a.y;  lo.z += a.z;  lo.w += a.w;
                hi.x += b2.x; hi.y += b2.y; hi.z += b2.z; hi.w += b2.w;
            }
            *(float4*)(op + row * 64 + dcol)     = lo;
            *(float4*)(op + row * 64 + dcol + 4) = hi;
        }
    }
}

extern "C" void kernel_launch(void* const* d_in, const int* in_sizes, int n_in,
                              void* d_out, int out_size) {
    const float* q     = (const float*)d_in[0];
    const float* k     = (const float*)d_in[1];
    const float* v     = (const float*)d_in[2];
    const float* prev  = (const float*)d_in[3];
    const float* mask  = (const float*)d_in[4];
    const float* scale = (const float*)d_in[5];

    float* out = (float*)d_out;                               // (4,16,1024,64)
    float* wts = out + (size_t)4 * 16 * 1024 * 64;            // (4,16,1024,1024)
    float* scr = wts + (size_t)4 * 16 * 1024 * 1024;          // (4,16,1024,1024)

    cudaFuncSetAttribute(attn_fused6_kernel,
                         cudaFuncAttributeMaxDynamicSharedMemorySize, SMEM_BYTES);

    attn_fused6_kernel<<<2048, 256, SMEM_BYTES>>>(q, k, v, prev, mask, scale,
                                                  out, wts, scr);
    (void)in_sizes; (void)n_in; (void)out_size;
}

// round 16
// speedup vs baseline: 1.0726x; 1.0726x over previous
#include <cuda_runtime.h>
#include <cuda_bf16.h>

typedef unsigned long long u64;
typedef unsigned int u32;
typedef unsigned short u16;

// ---- packed f32x2 helpers (FFMA2, pass B) ----
__device__ __forceinline__ void fma2(u64 &d, u64 a, u64 b) {
    asm volatile("fma.rn.f32x2 %0, %1, %2, %0;" : "+l"(d) : "l"(a), "l"(b));
}
__device__ __forceinline__ u64 dup2(float x) {
    u64 r; asm("mov.b64 %0, {%1, %1};" : "=l"(r) : "f"(x)); return r;
}
__device__ __forceinline__ float2 unpk(u64 v) {
    float lo, hi; asm("mov.b64 {%0, %1}, %2;" : "=f"(lo), "=f"(hi) : "l"(v));
    return make_float2(lo, hi);
}
__device__ __forceinline__ void cp16(u32 dst, const float* src) {
    asm volatile("cp.async.cg.shared.global [%0], [%1], 16;" :: "r"(dst), "l"(src));
}
__device__ __forceinline__ void cp_commit() { asm volatile("cp.async.commit_group;"); }
__device__ __forceinline__ void cp_wait0()  { asm volatile("cp.async.wait_group 0;"); }

// ---- mma.sync helpers (baseline PTX, works on .target sm_103) ----
__device__ __forceinline__ void ldsm4(u32* r, u32 addr) {
    asm volatile("ldmatrix.sync.aligned.m8n8.x4.shared.b16 {%0,%1,%2,%3}, [%4];"
        : "=r"(r[0]), "=r"(r[1]), "=r"(r[2]), "=r"(r[3]) : "r"(addr));
}
__device__ __forceinline__ void mma16816(float* c, const u32* a, const u32* b) {
    asm volatile("mma.sync.aligned.m16n8k16.row.col.f32.bf16.bf16.f32 "
        "{%0,%1,%2,%3}, {%4,%5,%6,%7}, {%8,%9}, {%0,%1,%2,%3};"
        : "+f"(c[0]), "+f"(c[1]), "+f"(c[2]), "+f"(c[3])
        : "r"(a[0]), "r"(a[1]), "r"(a[2]), "r"(a[3]), "r"(b[0]), "r"(b[1]));
}
__device__ __forceinline__ u32 bfsplit(float x, float y, u32 &lo) {
    __nv_bfloat16 hx = __float2bfloat16(x), hy = __float2bfloat16(y);
    float rx = x - __bfloat162float(hx), ry = y - __bfloat162float(hy);
    __nv_bfloat16 lx = __float2bfloat16(rx), ly = __float2bfloat16(ry);
    u32 h;
    lo = (u32)(*(u16*)&lx) | ((u32)(*(u16*)&ly) << 16);
    h  = (u32)(*(u16*)&hx) | ((u32)(*(u16*)&hy) << 16);
    return h;
}

#define VSEL(v,u) ((u)==0?(v).x:(u)==1?(v).y:(u)==2?(v).z:(v).w)

// q:(4,16,1024,64) k:(4,16,64,1024) v:(4,16,1024,64)
// prev:(4,16,1024,1024) mask:(1,16,1024,1024) scale:(1)
// out tuple: output ++ weights ++ scores

// ---- precomputed bf16 hi/lo K^T: [64 bh][1024 s][64 d] ----
__device__ __align__(128) u16 g_khi[64 * 1024 * 64];
__device__ __align__(128) u16 g_klo[64 * 1024 * 64];

// =============== Kernel 0: K transpose + bf16 split ===============
__global__ void __launch_bounds__(256, 4)
conv_k_kernel(const float* __restrict__ k)
{
    __shared__ float tile[64 * 68];
    const int bh = blockIdx.x >> 4;
    const int st = blockIdx.x & 15;          // 16 s-tiles of 64
    const float* kb = k + (size_t)bh * 65536 + st * 64;
    const int tid = threadIdx.x;

    #pragma unroll
    for (int j = 0; j < 4; j++) {
        int lin = j * 1024 + tid * 4;
        int d = lin >> 6, s = lin & 63;
        float4 v = *(const float4*)(kb + d * 1024 + s);
        tile[d * 68 + s + 0] = v.x;
        tile[d * 68 + s + 1] = v.y;
        tile[d * 68 + s + 2] = v.z;
        tile[d * 68 + s + 3] = v.w;
    }
    __syncthreads();

    const int s  = tid >> 2;
    const int dq = (tid & 3) * 16;
    u32 hi[8], lo[8];
    #pragma unroll
    for (int i = 0; i < 8; i++) {
        float x0 = tile[(dq + 2 * i)     * 68 + s];
        float x1 = tile[(dq + 2 * i + 1) * 68 + s];
        hi[i] = bfsplit(x0, x1, lo[i]);
    }
    size_t base = ((size_t)bh * 1024 + st * 64 + s) * 64 + dq;
    *(uint4*)(g_khi + base)     = make_uint4(hi[0], hi[1], hi[2], hi[3]);
    *(uint4*)(g_khi + base + 8) = make_uint4(hi[4], hi[5], hi[6], hi[7]);
    *(uint4*)(g_klo + base)     = make_uint4(lo[0], lo[1], lo[2], lo[3]);
    *(uint4*)(g_klo + base + 8) = make_uint4(lo[4], lo[5], lo[6], lo[7]);
}

// =============== Kernel 1: fused attention ===============
#define WS 132

// smem floats:
//  [0,2304)        q bf16 hi [32][72] + lo (9216 B total)
//  [2304,20736)    KT double buffer: 2 x 36864 B ([128 s][72] hi + lo)
//                  pass B overlay at [2304,22912): stage 16384 + w_s 4224
//  [22912,23040)   rsum_p[4][32]   [23040,23072) rinv[32]
#define SMEM_FLOATS 23072
#define SMEM_BYTES  (SMEM_FLOATS * 4)

__global__ void __launch_bounds__(256, 2)
attn_hmma_kernel(const float* __restrict__ q, const float* __restrict__ v,
                 const float* __restrict__ prev, const float* __restrict__ mask,
                 const float* __restrict__ scale_p,
                 float* __restrict__ out, float* __restrict__ wts, float* __restrict__ scr)
{
    extern __shared__ float sm[];
    char* smc = (char*)sm;
    float* rsum_p = sm + 22912;
    float* rinv   = sm + 23040;

    const int tid = threadIdx.x;
    const int bid = blockIdx.x;
    const int qt  = bid & 31;
    const int bh  = bid >> 5;
    const int h   = bh & 15;

    const float scale = scale_p[0];

    const float* qp = q    + ((size_t)bh * 1024 + (size_t)qt * 32) * 64;
    const float* vp = v    + (size_t)bh * 65536;
    const float* pp = prev + ((size_t)bh * 1024 + (size_t)qt * 32) * 1024;
    const float* mp = mask + ((size_t)h  * 1024 + (size_t)qt * 32) * 1024;
    float* op = out + ((size_t)bh * 1024 + (size_t)qt * 32) * 64;
    float* wp = wts + ((size_t)bh * 1024 + (size_t)qt * 32) * 1024;
    float* sp = scr + ((size_t)bh * 1024 + (size_t)qt * 32) * 1024;

    const u32 smem_base = (u32)__cvta_generic_to_shared(sm);
    const u32 kt0 = smem_base + 9216;

    // ---- stage KT chunk into double buffer (128 s x 64 d, bf16 hi+lo = 32 KB) ----
    #define STAGE_KT(tt) do {                                                       \
        u32 dstb = kt0 + ((tt) & 1) * 36864;                                        \
        const u16* srch = g_khi + ((size_t)bh * 1024 + (tt) * 128) * 64;            \
        const u16* srcl = g_klo + ((size_t)bh * 1024 + (tt) * 128) * 64;            \
        _Pragma("unroll")                                                           \
        for (int j = 0; j < 8; j++) {                                               \
            int cc = j * 256 + tid;                                                 \
            int hl = cc >> 10, s = (cc >> 3) & 127, d8 = cc & 7;                    \
            const u16* src = (hl ? srcl : srch) + s * 64 + d8 * 8;                  \
            cp16(dstb + hl * 18432 + s * 144 + d8 * 16, (const float*)src);         \
        }                                                                           \
        cp_commit();                                                                \
    } while (0)

    STAGE_KT(0);

    // ---- q -> bf16 hi/lo [32 m][72] rows (144 B stride) ----
    {
        int m = tid >> 3, d8 = (tid & 7) * 8;
        float4 v0 = *(const float4*)(qp + m * 64 + d8);
        float4 v1 = *(const float4*)(qp + m * 64 + d8 + 4);
        u32 h4[4], l4[4];
        h4[0] = bfsplit(v0.x, v0.y, l4[0]);
        h4[1] = bfsplit(v0.z, v0.w, l4[1]);
        h4[2] = bfsplit(v1.x, v1.y, l4[2]);
        h4[3] = bfsplit(v1.z, v1.w, l4[3]);
        *(uint4*)(smc + m * 144 + d8 * 2)        = make_uint4(h4[0], h4[1], h4[2], h4[3]);
        *(uint4*)(smc + 4608 + m * 144 + d8 * 2) = make_uint4(l4[0], l4[1], l4[2], l4[3]);
    }

    const int w  = tid >> 5;
    const int tx = tid & 31;

    // =============== Pass A: HMMA GEMM1 (8 chunks x 128 s) ===============
    // 8 warps = 2 m-groups (16 rows) x 4 s-groups (32 n)
    const int mg = w >> 2, sg = w & 3;
    const int m0 = mg * 16;
    const int n0 = sg * 32;
    const int r1 = m0 + (tx >> 2);
    const int sc2 = n0 + 2 * (tx & 3);

    const u32 a_addr_base = smem_base + (m0 + (tx & 15)) * 144 + ((tx >> 4) & 1) * 16;
    const u32 b_row = (n0 + (tx & 7) + ((tx >> 4) & 1) * 8) * 144 + ((tx >> 3) & 1) * 16;

    float lsum0 = 0.f, lsum1 = 0.f;

    for (int t = 0; t < 8; t++) {
        // prefetch prev (lands under HMMA)
        float2 pf0[4], pf1[4];
        #pragma unroll
        for (int nf = 0; nf < 4; nf++) {
            pf0[nf] = *(const float2*)(pp + r1 * 1024 + t * 128 + sc2 + nf * 8);
            pf1[nf] = *(const float2*)(pp + (r1 + 8) * 1024 + t * 128 + sc2 + nf * 8);
        }

        cp_wait0();
        __syncthreads();                 // KT chunk t staged; prior readers done
        if (t < 7) STAGE_KT(t + 1);      // other buffer, flies under compute

        const u32 ktb = kt0 + (t & 1) * 36864;
        float acc[4][4];
        #pragma unroll
        for (int i = 0; i < 4; i++)
            #pragma unroll
            for (int j = 0; j < 4; j++) acc[i][j] = 0.f;

        #pragma unroll
        for (int kk = 0; kk < 4; kk++) {
            u32 ah[4], al[4];
            ldsm4(ah, a_addr_base + kk * 32);
            ldsm4(al, a_addr_base + 4608 + kk * 32);
            #pragma unroll
            for (int jt = 0; jt < 2; jt++) {
                u32 baddr = ktb + b_row + jt * (16 * 144) + kk * 32;
                u32 bh4[4], bl4[4];
                ldsm4(bh4, baddr);
                ldsm4(bl4, baddr + 18432);
                mma16816(acc[2 * jt],     ah, bh4);
                mma16816(acc[2 * jt + 1], ah, bh4 + 2);
                mma16816(acc[2 * jt],     ah, bl4);
                mma16816(acc[2 * jt + 1], ah, bl4 + 2);
                mma16816(acc[2 * jt],     al, bh4);
                mma16816(acc[2 * jt + 1], al, bh4 + 2);
            }
        }

        // epilogue: score = acc*scale + prev -> gmem; exp -> rowsum
        #pragma unroll
        for (int nf = 0; nf < 4; nf++) {
            float2 s0, s1;
            s0.x = fmaf(acc[nf][0], scale, pf0[nf].x);
            s0.y = fmaf(acc[nf][1], scale, pf0[nf].y);
            s1.x = fmaf(acc[nf][2], scale, pf1[nf].x);
            s1.y = fmaf(acc[nf][3], scale, pf1[nf].y);
            *(float2*)(sp + r1 * 1024 + t * 128 + sc2 + nf * 8)       = s0;
            *(float2*)(sp + (r1 + 8) * 1024 + t * 128 + sc2 + nf * 8) = s1;
            lsum0 += __expf(s0.x) + __expf(s0.y);
            lsum1 += __expf(s1.x) + __expf(s1.y);
        }
    }

    // ---- rowsum reduce: 4 lanes share a row, then 4 s-groups via smem ----
    lsum0 += __shfl_xor_sync(0xffffffffu, lsum0, 1);
    lsum0 += __shfl_xor_sync(0xffffffffu, lsum0, 2);
    lsum1 += __shfl_xor_sync(0xffffffffu, lsum1, 1);
    lsum1 += __shfl_xor_sync(0xffffffffu, lsum1, 2);
    if ((tx & 3) == 0) {
        rsum_p[sg * 32 + r1]     = lsum0;
        rsum_p[sg * 32 + r1 + 8] = lsum1;
    }
    __syncthreads();
    if (tid < 32)
        rinv[tid] = 1.0f / (rsum_p[tid] + rsum_p[32 + tid] + rsum_p[64 + tid] + rsum_p[96 + tid]);
    __syncthreads();    // also: all sp STGs done before cp.async re-reads

    // =============== Pass B: weights + output GEMM (R13, proven) ===============
    float* stage   = sm + 2304;                  // 2 x (scores 4096 + mask 4096)
    float* w_s     = sm + 2304 + 16384;          // [32][132]
    float* scratch = sm + 2304;                  // combine overlay
    const u32 st_sh = (u32)__cvta_generic_to_shared(stage);

    // stage chunk 0 -> buf 0
    #pragma unroll
    for (int j = 0; j < 4; j++) {
        int idx = j * 1024 + tid * 4;
        int row = idx >> 7, scol = idx & 127;
        cp16(st_sh + idx * 4,          sp + row * 1024 + scol);
        cp16(st_sh + (4096 + idx) * 4, mp + row * 1024 + scol);
    }
    cp_commit();

    const int sub = w >> 1, dh = w & 1;          // 4 s-subgroups (32 s) x 2 d-halves
    const int txg = tx & 3, tyg = tx >> 2;
    const int dcol = dh * 32 + txg * 8;
    const int rr = tid >> 3, t8 = tid & 7;
    const float ivr = rinv[rr];

    u64 oacc[4][4];
    #pragma unroll
    for (int i = 0; i < 4; i++)
        #pragma unroll
        for (int p = 0; p < 4; p++) oacc[i][p] = 0ull;

    for (int c = 0; c < 8; c++) {
        const int b = c & 1;
        const float* sb_s = stage + b * 8192;
        const float* mb_s = sb_s + 4096;

        cp_wait0();
        __syncthreads();

        if (c < 7) {
            #pragma unroll
            for (int j = 0; j < 4; j++) {
                int idx = j * 1024 + tid * 4;
                int row = idx >> 7, scol = idx & 127;
                cp16(st_sh + ((b ^ 1) * 8192 + idx) * 4,        sp + row * 1024 + (c + 1) * 128 + scol);
                cp16(st_sh + ((b ^ 1) * 8192 + 4096 + idx) * 4, mp + row * 1024 + (c + 1) * 128 + scol);
            }
            cp_commit();
        }

        #pragma unroll
        for (int j = 0; j < 4; j++) {
            int sl = t8 * 4 + j * 32;
            float4 sv = *(const float4*)(sb_s + rr * 128 + sl);
            float4 mv = *(const float4*)(mb_s + rr * 128 + sl);
            float4 w4;
            w4.x = __expf(sv.x) * ivr * mv.x;
            w4.y = __expf(sv.y) * ivr * mv.y;
            w4.z = __expf(sv.z) * ivr * mv.z;
            w4.w = __expf(sv.w) * ivr * mv.w;
            *(float4*)(wp + rr * 1024 + c * 128 + sl) = w4;
            *(float4*)(w_s + rr * WS + sl)            = w4;
        }
        __syncthreads();

        const int sb = sub * 32;
        const float* vbase = vp + ((size_t)(c * 128 + sb)) * 64 + dcol;

        #pragma unroll 2
        for (int ss = 0; ss < 32; ss += 4) {
            float4 wv0 = *(const float4*)(w_s + (tyg +  0) * WS + sb + ss);
            float4 wv1 = *(const float4*)(w_s + (tyg +  8) * WS + sb + ss);
            float4 wv2 = *(const float4*)(w_s + (tyg + 16) * WS + sb + ss);
            float4 wv3 = *(const float4*)(w_s + (tyg + 24) * WS + sb + ss);
            ulonglong2 va[4], vb[4];
            #pragma unroll
            for (int u = 0; u < 4; u++) {
                va[u] = *(const ulonglong2*)(vbase + (ss + u) * 64);
                vb[u] = *(const ulonglong2*)(vbase + (ss + u) * 64 + 4);
            }
            #pragma unroll
            for (int u = 0; u < 4; u++) {
                u64 w0 = dup2(VSEL(wv0, u));
                u64 w1 = dup2(VSEL(wv1, u));
                u64 w2 = dup2(VSEL(wv2, u));
                u64 w3 = dup2(VSEL(wv3, u));
                fma2(oacc[0][0], w0, va[u].x); fma2(oacc[0][1], w0, va[u].y);
                fma2(oacc[0][2], w0, vb[u].x); fma2(oacc[0][3], w0, vb[u].y);
                fma2(oacc[1][0], w1, va[u].x); fma2(oacc[1][1], w1, va[u].y);
                fma2(oacc[1][2], w1, vb[u].x); fma2(oacc[1][3], w1, vb[u].y);
                fma2(oacc[2][0], w2, va[u].x); fma2(oacc[2][1], w2, va[u].y);
                fma2(oacc[2][2], w2, vb[u].x); fma2(oacc[2][3], w2, vb[u].y);
                fma2(oacc[3][0], w3, va[u].x); fma2(oacc[3][1], w3, va[u].y);
                fma2(oacc[3][2], w3, vb[u].x); fma2(oacc[3][3], w3, vb[u].y);
            }
        }
    }

    // ---- combine the 4 s-subgroup partials ----
    __syncthreads();
    if (sub > 0) {
        #pragma unroll
        for (int i = 0; i < 4; i++) {
            float2 p0 = unpk(oacc[i][0]), p1 = unpk(oacc[i][1]);
            float2 p2 = unpk(oacc[i][2]), p3 = unpk(oacc[i][3]);
            float* bptr = scratch + (sub - 1) * 2176 + (tyg + 8 * i) * 68 + dcol;
            *(float4*)(bptr)     = make_float4(p0.x, p0.y, p1.x, p1.y);
            *(float4*)(bptr + 4) = make_float4(p2.x, p2.y, p3.x, p3.y);
        }
    }
    __syncthreads();
    if (sub == 0) {
        #pragma unroll
        for (int i = 0; i < 4; i++) {
            int row = tyg + 8 * i;
            float2 p0 = unpk(oacc[i][0]), p1 = unpk(oacc[i][1]);
            float2 p2 = unpk(oacc[i][2]), p3 = unpk(oacc[i][3]);
            float4 lo = make_float4(p0.x, p0.y, p1.x, p1.y);
            float4 hi = make_float4(p2.x, p2.y, p3.x, p3.y);
            #pragma unroll
            for (int s2 = 0; s2 < 3; s2++) {
                const float* bptr = scratch + s2 * 2176 + row * 68 + dcol;
                float4 a  = *(const float4*)(bptr);
                float4 b2 = *(const float4*)(bptr + 4);
                lo.x += a.x;  lo.y += a.y;  lo.z += a.z;  lo.w += a.w;
                hi.x += b2.x; hi.y += b2.y; hi.z += b2.z; hi.w += b2.w;
            }
            *(float4*)(op + row * 64 + dcol)     = lo;
            *(float4*)(op + row * 64 + dcol + 4) = hi;
        }
    }
}

extern "C" void kernel_launch(void* const* d_in, const int* in_sizes, int n_in,
                              void* d_out, int out_size) {
    const float* q     = (const float*)d_in[0];
    const float* k     = (const float*)d_in[1];
    const float* v     = (const float*)d_in[2];
    const float* prev  = (const float*)d_in[3];
    const float* mask  = (const float*)d_in[4];
    const float* scale = (const float*)d_in[5];

    float* out = (float*)d_out;                               // (4,16,1024,64)
    float* wts = out + (size_t)4 * 16 * 1024 * 64;            // (4,16,1024,1024)
    float* scr = wts + (size_t)4 * 16 * 1024 * 1024;          // (4,16,1024,1024)

    conv_k_kernel<<<1024, 256>>>(k);

    cudaFuncSetAttribute(attn_hmma_kernel,
                         cudaFuncAttributeMaxDynamicSharedMemorySize, SMEM_BYTES);
    attn_hmma_kernel<<<2048, 256, SMEM_BYTES>>>(q, v, prev, mask, scale,
                                                out, wts, scr);
    (void)in_sizes; (void)n_in; (void)out_size;
}

// round 17
// speedup vs baseline: 1.3970x; 1.3024x over previous
#include <cuda_runtime.h>
#include <cuda_bf16.h>

typedef unsigned long long u64;
typedef unsigned int u32;
typedef unsigned short u16;

__device__ __forceinline__ void cp16(u32 dst, const void* src) {
    asm volatile("cp.async.cg.shared.global [%0], [%1], 16;" :: "r"(dst), "l"(src));
}
__device__ __forceinline__ void cp_commit() { asm volatile("cp.async.commit_group;"); }
__device__ __forceinline__ void cp_wait0()  { asm volatile("cp.async.wait_group 0;"); }
__device__ __forceinline__ void cp_wait1()  { asm volatile("cp.async.wait_group 1;"); }

// ---- mma.sync helpers (baseline PTX, works on .target sm_103) ----
__device__ __forceinline__ void ldsm4(u32* r, u32 addr) {
    asm volatile("ldmatrix.sync.aligned.m8n8.x4.shared.b16 {%0,%1,%2,%3}, [%4];"
        : "=r"(r[0]), "=r"(r[1]), "=r"(r[2]), "=r"(r[3]) : "r"(addr));
}
__device__ __forceinline__ void mma16816(float* c, const u32* a, const u32* b) {
    asm volatile("mma.sync.aligned.m16n8k16.row.col.f32.bf16.bf16.f32 "
        "{%0,%1,%2,%3}, {%4,%5,%6,%7}, {%8,%9}, {%0,%1,%2,%3};"
        : "+f"(c[0]), "+f"(c[1]), "+f"(c[2]), "+f"(c[3])
        : "r"(a[0]), "r"(a[1]), "r"(a[2]), "r"(a[3]), "r"(b[0]), "r"(b[1]));
}
__device__ __forceinline__ u32 bfsplit(float x, float y, u32 &lo) {
    __nv_bfloat16 hx = __float2bfloat16(x), hy = __float2bfloat16(y);
    float rx = x - __bfloat162float(hx), ry = y - __bfloat162float(hy);
    __nv_bfloat16 lx = __float2bfloat16(rx), ly = __float2bfloat16(ry);
    u32 h;
    lo = (u32)(*(u16*)&lx) | ((u32)(*(u16*)&ly) << 16);
    h  = (u32)(*(u16*)&hx) | ((u32)(*(u16*)&hy) << 16);
    return h;
}

// q:(4,16,1024,64) k:(4,16,64,1024) v:(4,16,1024,64)
// prev:(4,16,1024,1024) mask:(1,16,1024,1024) scale:(1)
// out tuple: output ++ weights ++ scores

// ---- precomputed bf16 hi/lo: K^T [64 bh][1024 s][64 d], V^T [64 bh][64 d][1024 s] ----
__device__ __align__(128) u16 g_khi[64 * 1024 * 64];
__device__ __align__(128) u16 g_klo[64 * 1024 * 64];
__device__ __align__(128) u16 g_vthi[64 * 64 * 1024];
__device__ __align__(128) u16 g_vtlo[64 * 64 * 1024];

// =============== Kernel 0: K / V transpose + bf16 split ===============
__global__ void __launch_bounds__(256, 4)
conv_kv_kernel(const float* __restrict__ k, const float* __restrict__ v)
{
    __shared__ float tile[64 * 68];
    const int isV = blockIdx.x >> 10;
    const int bh = (blockIdx.x >> 4) & 63;
    const int st = blockIdx.x & 15;          // 16 s-tiles of 64
    const int tid = threadIdx.x;

    if (!isV) {
        // ---- K path: K[d][s] -> KT[s][d] hi/lo ----
        const float* kb = k + (size_t)bh * 65536 + st * 64;
        #pragma unroll
        for (int j = 0; j < 4; j++) {
            int lin = j * 1024 + tid * 4;
            int d = lin >> 6, s = lin & 63;
            float4 vv = *(const float4*)(kb + d * 1024 + s);
            tile[d * 68 + s + 0] = vv.x;
            tile[d * 68 + s + 1] = vv.y;
            tile[d * 68 + s + 2] = vv.z;
            tile[d * 68 + s + 3] = vv.w;
        }
        __syncthreads();
        const int s  = tid >> 2;
        const int dq = (tid & 3) * 16;
        u32 hi[8], lo[8];
        #pragma unroll
        for (int i = 0; i < 8; i++) {
            float x0 = tile[(dq + 2 * i)     * 68 + s];
            float x1 = tile[(dq + 2 * i + 1) * 68 + s];
            hi[i] = bfsplit(x0, x1, lo[i]);
        }
        size_t base = ((size_t)bh * 1024 + st * 64 + s) * 64 + dq;
        *(uint4*)(g_khi + base)     = make_uint4(hi[0], hi[1], hi[2], hi[3]);
        *(uint4*)(g_khi + base + 8) = make_uint4(hi[4], hi[5], hi[6], hi[7]);
        *(uint4*)(g_klo + base)     = make_uint4(lo[0], lo[1], lo[2], lo[3]);
        *(uint4*)(g_klo + base + 8) = make_uint4(lo[4], lo[5], lo[6], lo[7]);
    } else {
        // ---- V path: V[s][d] -> VT[d][s] hi/lo ----
        const float* vb = v + (size_t)bh * 65536 + (size_t)st * 64 * 64;
        #pragma unroll
        for (int j = 0; j < 4; j++) {
            int lin = j * 1024 + tid * 4;
            int s = lin >> 6, d0 = lin & 63;
            float4 vv = *(const float4*)(vb + s * 64 + d0);
            tile[s * 68 + d0 + 0] = vv.x;
            tile[s * 68 + d0 + 1] = vv.y;
            tile[s * 68 + d0 + 2] = vv.z;
            tile[s * 68 + d0 + 3] = vv.w;
        }
        __syncthreads();
        const int d  = tid >> 2;
        const int sg = (tid & 3) * 16;
        u32 hi[8], lo[8];
        #pragma unroll
        for (int i = 0; i < 8; i++) {
            float x0 = tile[(sg + 2 * i)     * 68 + d];
            float x1 = tile[(sg + 2 * i + 1) * 68 + d];
            hi[i] = bfsplit(x0, x1, lo[i]);
        }
        size_t base = ((size_t)bh * 64 + d) * 1024 + st * 64 + sg;
        *(uint4*)(g_vthi + base)     = make_uint4(hi[0], hi[1], hi[2], hi[3]);
        *(uint4*)(g_vthi + base + 8) = make_uint4(hi[4], hi[5], hi[6], hi[7]);
        *(uint4*)(g_vtlo + base)     = make_uint4(lo[0], lo[1], lo[2], lo[3]);
        *(uint4*)(g_vtlo + base + 8) = make_uint4(lo[4], lo[5], lo[6], lo[7]);
    }
}

// =============== Kernel 1: fused attention ===============
// smem floats:
//  [0,2304)        q bf16 hi [32][72] + lo (9216 B)
//  [2304,20736)    pass A: KT double buffer 2 x 36864 B
//  pass B overlay: [2304,10496) scores stage dbl 2x4096 fl
//                  [10496,19200) VT buf (hi 17408 B + lo 17408 B)
//                  [19200,23552) w bf16 hi+lo (2 x 8704 B)
//  [23552,23680)   rsum_p[4][32]   [23680,23712) rinv[32]
#define SMEM_FLOATS 23712
#define SMEM_BYTES  (SMEM_FLOATS * 4)

__global__ void __launch_bounds__(256, 2)
attn_hmma2_kernel(const float* __restrict__ q, const float* __restrict__ prev,
                  const float* __restrict__ mask, const float* __restrict__ scale_p,
                  float* __restrict__ out, float* __restrict__ wts, float* __restrict__ scr)
{
    extern __shared__ float sm[];
    char* smc = (char*)sm;
    float* rsum_p = sm + 23552;
    float* rinv   = sm + 23680;

    const int tid = threadIdx.x;
    const int bid = blockIdx.x;
    const int qt  = bid & 31;
    const int bh  = bid >> 5;
    const int h   = bh & 15;

    const float scale = scale_p[0];

    const float* qp = q    + ((size_t)bh * 1024 + (size_t)qt * 32) * 64;
    const float* pp = prev + ((size_t)bh * 1024 + (size_t)qt * 32) * 1024;
    const float* mp = mask + ((size_t)h  * 1024 + (size_t)qt * 32) * 1024;
    float* op = out + ((size_t)bh * 1024 + (size_t)qt * 32) * 64;
    float* wp = wts + ((size_t)bh * 1024 + (size_t)qt * 32) * 1024;
    float* sp = scr + ((size_t)bh * 1024 + (size_t)qt * 32) * 1024;

    const u32 smem_base = (u32)__cvta_generic_to_shared(sm);
    const u32 kt0 = smem_base + 9216;

    // ---- stage KT chunk into double buffer (128 s x 64 d, bf16 hi+lo) ----
    #define STAGE_KT(tt) do {                                                       \
        u32 dstb = kt0 + ((tt) & 1) * 36864;                                        \
        const u16* srch = g_khi + ((size_t)bh * 1024 + (tt) * 128) * 64;            \
        const u16* srcl = g_klo + ((size_t)bh * 1024 + (tt) * 128) * 64;            \
        _Pragma("unroll")                                                           \
        for (int j = 0; j < 8; j++) {                                               \
            int cc = j * 256 + tid;                                                 \
            int hl = cc >> 10, s = (cc >> 3) & 127, d8 = cc & 7;                    \
            const u16* src = (hl ? srcl : srch) + s * 64 + d8 * 8;                  \
            cp16(dstb + hl * 18432 + s * 144 + d8 * 16, src);                       \
        }                                                                           \
        cp_commit();                                                                \
    } while (0)

    STAGE_KT(0);

    // ---- q -> bf16 hi/lo [32 m][72] rows (144 B stride) ----
    {
        int m = tid >> 3, d8 = (tid & 7) * 8;
        float4 v0 = *(const float4*)(qp + m * 64 + d8);
        float4 v1 = *(const float4*)(qp + m * 64 + d8 + 4);
        u32 h4[4], l4[4];
        h4[0] = bfsplit(v0.x, v0.y, l4[0]);
        h4[1] = bfsplit(v0.z, v0.w, l4[1]);
        h4[2] = bfsplit(v1.x, v1.y, l4[2]);
        h4[3] = bfsplit(v1.z, v1.w, l4[3]);
        *(uint4*)(smc + m * 144 + d8 * 2)        = make_uint4(h4[0], h4[1], h4[2], h4[3]);
        *(uint4*)(smc + 4608 + m * 144 + d8 * 2) = make_uint4(l4[0], l4[1], l4[2], l4[3]);
    }

    const int w  = tid >> 5;
    const int tx = tid & 31;

    // =============== Pass A: HMMA GEMM1 (proven R16) ===============
    const int mg = w >> 2, sg = w & 3;
    const int m0 = mg * 16;
    const int n0 = sg * 32;
    const int r1 = m0 + (tx >> 2);
    const int sc2 = n0 + 2 * (tx & 3);

    const u32 a_addr_base = smem_base + (m0 + (tx & 15)) * 144 + ((tx >> 4) & 1) * 16;
    const u32 b_row = (n0 + (tx & 7) + ((tx >> 4) & 1) * 8) * 144 + ((tx >> 3) & 1) * 16;

    float lsum0 = 0.f, lsum1 = 0.f;

    for (int t = 0; t < 8; t++) {
        float2 pf0[4], pf1[4];
        #pragma unroll
        for (int nf = 0; nf < 4; nf++) {
            pf0[nf] = *(const float2*)(pp + r1 * 1024 + t * 128 + sc2 + nf * 8);
            pf1[nf] = *(const float2*)(pp + (r1 + 8) * 1024 + t * 128 + sc2 + nf * 8);
        }

        cp_wait0();
        __syncthreads();
        if (t < 7) STAGE_KT(t + 1);

        const u32 ktb = kt0 + (t & 1) * 36864;
        float acc[4][4];
        #pragma unroll
        for (int i = 0; i < 4; i++)
            #pragma unroll
            for (int j = 0; j < 4; j++) acc[i][j] = 0.f;

        #pragma unroll
        for (int kk = 0; kk < 4; kk++) {
            u32 ah[4], al[4];
            ldsm4(ah, a_addr_base + kk * 32);
            ldsm4(al, a_addr_base + 4608 + kk * 32);
            #pragma unroll
            for (int jt = 0; jt < 2; jt++) {
                u32 baddr = ktb + b_row + jt * (16 * 144) + kk * 32;
                u32 bh4[4], bl4[4];
                ldsm4(bh4, baddr);
                ldsm4(bl4, baddr + 18432);
                mma16816(acc[2 * jt],     ah, bh4);
                mma16816(acc[2 * jt + 1], ah, bh4 + 2);
                mma16816(acc[2 * jt],     ah, bl4);
                mma16816(acc[2 * jt + 1], ah, bl4 + 2);
                mma16816(acc[2 * jt],     al, bh4);
                mma16816(acc[2 * jt + 1], al, bh4 + 2);
            }
        }

        #pragma unroll
        for (int nf = 0; nf < 4; nf++) {
            float2 s0, s1;
            s0.x = fmaf(acc[nf][0], scale, pf0[nf].x);
            s0.y = fmaf(acc[nf][1], scale, pf0[nf].y);
            s1.x = fmaf(acc[nf][2], scale, pf1[nf].x);
            s1.y = fmaf(acc[nf][3], scale, pf1[nf].y);
            *(float2*)(sp + r1 * 1024 + t * 128 + sc2 + nf * 8)       = s0;
            *(float2*)(sp + (r1 + 8) * 1024 + t * 128 + sc2 + nf * 8) = s1;
            lsum0 += __expf(s0.x) + __expf(s0.y);
            lsum1 += __expf(s1.x) + __expf(s1.y);
        }
    }

    // ---- rowsum reduce ----
    lsum0 += __shfl_xor_sync(0xffffffffu, lsum0, 1);
    lsum0 += __shfl_xor_sync(0xffffffffu, lsum0, 2);
    lsum1 += __shfl_xor_sync(0xffffffffu, lsum1, 1);
    lsum1 += __shfl_xor_sync(0xffffffffu, lsum1, 2);
    if ((tx & 3) == 0) {
        rsum_p[sg * 32 + r1]     = lsum0;
        rsum_p[sg * 32 + r1 + 8] = lsum1;
    }
    __syncthreads();
    if (tid < 32)
        rinv[tid] = 1.0f / (rsum_p[tid] + rsum_p[32 + tid] + rsum_p[64 + tid] + rsum_p[96 + tid]);
    __syncthreads();    // all sp STGs done; pass A smem dead

    // =============== Pass B: weights (bf16 split) + HMMA GEMM2 ===============
    const u32 st_sh = smem_base + 9216;          // scores stage: 2 x 16384 B
    const u32 vt_sh = smem_base + 41984;         // VT buf: hi 17408 + lo 17408
    const u32 w_sh  = smem_base + 76800;         // w bf16: hi 8704 + lo 8704
    char* w_hi_c = smc + 76800;
    char* w_lo_c = w_hi_c + 8704;

    // stage scores chunk -> buf (chunk&1)
    #define STAGE_SC(cc) do {                                                       \
        int _b = (cc) & 1;                                                          \
        _Pragma("unroll")                                                           \
        for (int j = 0; j < 4; j++) {                                               \
            int idx = j * 1024 + tid * 4;                                           \
            int row = idx >> 7, scol = idx & 127;                                   \
            cp16(st_sh + (_b * 4096 + idx) * 4, sp + row * 1024 + (cc) * 128 + scol); \
        }                                                                           \
        cp_commit();                                                                \
    } while (0)

    // stage VT chunk (single buffer): [64 d][128 s] bf16 hi+lo, 272 B rows
    #define STAGE_VT(cc) do {                                                       \
        const u16* svh = g_vthi + (size_t)bh * 65536 + (cc) * 128;                  \
        const u16* svl = g_vtlo + (size_t)bh * 65536 + (cc) * 128;                  \
        _Pragma("unroll")                                                           \
        for (int j = 0; j < 8; j++) {                                               \
            int cc2 = j * 256 + tid;                                                \
            int hl = cc2 >> 10, d = (cc2 >> 4) & 63, ch = cc2 & 15;                 \
            const u16* src = (hl ? svl : svh) + (size_t)d * 1024 + ch * 8;          \
            cp16(vt_sh + hl * 17408 + d * 272 + ch * 16, src);                      \
        }                                                                           \
        cp_commit();                                                                \
    } while (0)

    const int rr = tid >> 3, t8 = tid & 7;       // conversion map
    const float ivr = rinv[rr];

    const int mg2 = w >> 2, dg = w & 3;          // 2 m-groups x 4 d-groups (n16)
    const u32 aw_base = w_sh + (mg2 * 16 + (tx & 15)) * 272 + ((tx >> 4) & 1) * 16;
    const u32 bv_base = vt_sh + (dg * 16 + (tx & 7) + ((tx >> 4) & 1) * 8) * 272 + ((tx >> 3) & 1) * 16;

    float oacc[2][4];
    #pragma unroll
    for (int nt = 0; nt < 2; nt++)
        #pragma unroll
        for (int j = 0; j < 4; j++) oacc[nt][j] = 0.f;

    STAGE_SC(0);

    for (int c = 0; c < 8; c++) {
        // prefetch mask for this chunk (L2-hot, 4x reuse across b)
        float4 mv4[4];
        #pragma unroll
        for (int j = 0; j < 4; j++)
            mv4[j] = *(const float4*)(mp + rr * 1024 + c * 128 + t8 * 4 + j * 32);

        cp_wait0();              // scores(c) staged
        __syncthreads();         // + w/VT free of prior readers

        STAGE_VT(c);             // flies under conversion
        if (c < 7) STAGE_SC(c + 1);

        // conversion: w = exp(score)*inv*mask -> gmem wts (fp32) + smem bf16 hi/lo
        const float* sb_s = sm + 2304 + (c & 1) * 4096;
        #pragma unroll
        for (int j = 0; j < 4; j++) {
            int sl = t8 * 4 + j * 32;
            float4 sv = *(const float4*)(sb_s + rr * 128 + sl);
            float4 w4;
            w4.x = __expf(sv.x) * ivr * mv4[j].x;
            w4.y = __expf(sv.y) * ivr * mv4[j].y;
            w4.z = __expf(sv.z) * ivr * mv4[j].z;
            w4.w = __expf(sv.w) * ivr * mv4[j].w;
            *(float4*)(wp + rr * 1024 + c * 128 + sl) = w4;
            u32 lo0, lo1;
            u32 hi0 = bfsplit(w4.x, w4.y, lo0);
            u32 hi1 = bfsplit(w4.z, w4.w, lo1);
            *(uint2*)(w_hi_c + rr * 272 + sl * 2) = make_uint2(hi0, hi1);
            *(uint2*)(w_lo_c + rr * 272 + sl * 2) = make_uint2(lo0, lo1);
        }

        if (c < 7) cp_wait1();   // VT(c) done (stage(c+1) may still fly)
        else       cp_wait0();
        __syncthreads();         // w bf16 + VT visible

        // GEMM2 chunk: oacc += w[m16][k128] x VT[n16][k128], 3-term split
        #pragma unroll
        for (int kk = 0; kk < 8; kk++) {
            u32 ah[4], al[4], bh4[4], bl4[4];
            ldsm4(ah, aw_base + kk * 32);
            ldsm4(al, aw_base + 8704 + kk * 32);
            ldsm4(bh4, bv_base + kk * 32);
            ldsm4(bl4, bv_base + 17408 + kk * 32);
            mma16816(oacc[0], ah, bh4);
            mma16816(oacc[1], ah, bh4 + 2);
            mma16816(oacc[0], ah, bl4);
            mma16816(oacc[1], ah, bl4 + 2);
            mma16816(oacc[0], al, bh4);
            mma16816(oacc[1], al, bh4 + 2);
        }
    }

    // ---- output write: each warp owns its complete m16 x n16 tile ----
    {
        int r1b = mg2 * 16 + (tx >> 2);
        int cb  = dg * 16 + 2 * (tx & 3);
        #pragma unroll
        for (int nt = 0; nt < 2; nt++) {
            *(float2*)(op + r1b * 64 + cb + nt * 8)       = make_float2(oacc[nt][0], oacc[nt][1]);
            *(float2*)(op + (r1b + 8) * 64 + cb + nt * 8) = make_float2(oacc[nt][2], oacc[nt][3]);
        }
    }
}

extern "C" void kernel_launch(void* const* d_in, const int* in_sizes, int n_in,
                              void* d_out, int out_size) {
    const float* q     = (const float*)d_in[0];
    const float* k     = (const float*)d_in[1];
    const float* v     = (const float*)d_in[2];
    const float* prev  = (const float*)d_in[3];
    const float* mask  = (const float*)d_in[4];
    const float* scale = (const float*)d_in[5];

    float* out = (float*)d_out;                               // (4,16,1024,64)
    float* wts = out + (size_t)4 * 16 * 1024 * 64;            // (4,16,1024,1024)
    float* scr = wts + (size_t)4 * 16 * 1024 * 1024;          // (4,16,1024,1024)

    conv_kv_kernel<<<2048, 256>>>(k, v);

    cudaFuncSetAttribute(attn_hmma2_kernel,
                         cudaFuncAttributeMaxDynamicSharedMemorySize, SMEM_BYTES);
    attn_hmma2_kernel<<<2048, 256, SMEM_BYTES>>>(q, prev, mask, scale,
                                                 out, wts, scr);
    (void)in_sizes; (void)n_in; (void)out_size;
}